// round 10
// baseline (speedup 1.0000x reference)
#include <cuda_runtime.h>
#include <math.h>
#include <stdint.h>

#define B_ 8
#define N_ 2048
#define W_ 64
#define R_ 4
#define EPS_ 1e-8f
#define TI_ 128

typedef unsigned long long u64;

// ---------------- device scratch ----------------
__device__ float g_fwd [B_*R_*N_];   // fully corrected forward weights
__device__ float g_bwd [B_*R_*N_];   // atomically accumulated bwd core sums
__device__ float g_bc  [B_*R_*N_];   // bwd correction: pn*S - ell*prn
__device__ float g_gate[B_*R_*3];
__device__ float g_P   [B_*R_];
__device__ float g_S   [B_*R_];
__device__ float g_beta[B_*R_];
__device__ float g_kn  [B_*R_];
__device__ float g_om  [B_*R_*W_];   // main (fwd+bwd) output accum
__device__ float g_ocw [B_*R_*W_];   // content output accum (unnormalized)
__device__ float g_Z   [B_*R_];      // softmax partition sums

// ---------------- f32x2 helpers ----------------
__device__ __forceinline__ u64 pk(float a, float b){
    u64 r; asm("mov.b64 %0,{%1,%2};" : "=l"(r) : "f"(a), "f"(b)); return r;
}
__device__ __forceinline__ void upk(u64 x, float& a, float& b){
    asm("mov.b64 {%0,%1},%2;" : "=f"(a), "=f"(b) : "l"(x));
}
__device__ __forceinline__ u64 add2(u64 a, u64 b){
    u64 d; asm("add.rn.f32x2 %0,%1,%2;" : "=l"(d) : "l"(a), "l"(b)); return d;
}
__device__ __forceinline__ u64 sub2(u64 a, u64 b){
    u64 d; asm("sub.rn.f32x2 %0,%1,%2;" : "=l"(d) : "l"(a), "l"(b)); return d;
}
__device__ __forceinline__ u64 mul2(u64 a, u64 b){
    u64 d; asm("mul.rn.f32x2 %0,%1,%2;" : "=l"(d) : "l"(a), "l"(b)); return d;
}
__device__ __forceinline__ u64 fma2(u64 a, u64 b, u64 c){
    u64 d; asm("fma.rn.f32x2 %0,%1,%2,%3;" : "=l"(d) : "l"(a), "l"(b), "l"(c)); return d;
}

// ================= k_pre: P,S,beta,gates,key-norms; zero accumulators. 32 blocks x 256 =================
__global__ void __launch_bounds__(256)
k_pre(const float* __restrict__ controls, const float* __restrict__ ww,
      const float* __restrict__ p, const float* __restrict__ prw)
{
    int br = blockIdx.x, b = br >> 2, r = br & 3;
    int tid = threadIdx.x, warp = tid >> 5, lane = tid & 31;
    __shared__ u64 s_r1[8];
    __shared__ float s_k[2];

    for (int k = tid; k < N_; k += 256) g_bwd[br*N_ + k] = 0.f;
    if (tid < 64) { g_om[br*64 + tid] = 0.f; g_ocw[br*64 + tid] = 0.f; }
    if (tid == 0) g_Z[br] = 0.f;

    // key norm for this (b,r)
    float kq = 0.f;
    if (tid < 64) { float kv = controls[b*272 + r*64 + tid]; kq = kv*kv; }
    #pragma unroll
    for (int m = 16; m; m >>= 1) kq += __shfl_xor_sync(~0u, kq, m);
    if (lane == 0 && warp < 2) s_k[warp] = kq;

    float accP = 0.f, accS = 0.f;
    for (int k = tid; k < N_; k += 256) {
        float t = prw[br*N_ + k];
        accP += p [b*N_ + k]*t;
        accS += ww[b*N_ + k]*t;
    }
    u64 pp = pk(accP, accS);
    #pragma unroll
    for (int m = 16; m; m >>= 1) pp = add2(pp, __shfl_xor_sync(~0u, pp, m));
    if (lane == 0) s_r1[warp] = pp;
    __syncthreads();
    if (tid == 0) {
        float P = 0.f, S = 0.f;
        #pragma unroll
        for (int i = 0; i < 8; ++i) { float x, y; upk(s_r1[i], x, y); P += x; S += y; }
        g_P[br] = P; g_S[br] = S;
        g_kn[br] = sqrtf(s_k[0] + s_k[1]);
        float x = controls[b*272 + 256 + r];
        g_beta[br] = 1.f + ((x > 15.f) ? x : log1pf(__expf(x)));
        float e0 = controls[b*272 + 260 + r*3 + 0];
        float e1 = controls[b*272 + 260 + r*3 + 1];
        float e2 = controls[b*272 + 260 + r*3 + 2];
        float mm = fmaxf(e0, fmaxf(e1, e2));
        float x0 = __expf(e0-mm), x1 = __expf(e1-mm), x2 = __expf(e2-mm);
        float inv = 1.f/(x0+x1+x2);
        g_gate[br*3+0] = x0*inv; g_gate[br*3+1] = x1*inv; g_gate[br*3+2] = x2*inv;
    }
}

// ================= k_stream: one pass over L (R8-proven depth-3 LDG stream) =================
#define SP(sel,row,w) s_part[(((sel)*128 + (row))*16) + (w)]

__global__ void __launch_bounds__(512, 1)
k_stream(const float* __restrict__ L, const float* __restrict__ ww,
         const float* __restrict__ prw, const float* __restrict__ p)
{
    __shared__ u64   s_part[2*128*16];     // 32 KB fwd partials
    __shared__ float s_a[TI_];
    __shared__ float s_pi[R_*TI_];
    __shared__ float s_diag[TI_];

    int b = blockIdx.x >> 4, tile = blockIdx.x & 15, i0 = tile*TI_;
    int tid = threadIdx.x, w = tid >> 5, lane = tid & 31;
    int half = lane >> 4, h = lane & 15;

    if (tid < TI_) {
        s_a[tid]    = 1.f - ww[b*N_ + i0 + tid];
        s_diag[tid] = __ldg(L + ((size_t)(b*N_ + i0 + tid))*N_ + i0 + tid);
    }
    if (tid < R_*TI_) s_pi[tid] = prw[(b*4 + (tid >> 7))*N_ + i0 + (tid & 127)];
    __syncthreads();

    int jA = w*128 + h*4, jB = jA + 64;
    u64 pj[4][4];
    #pragma unroll
    for (int r = 0; r < 4; ++r) {
        float4 A  = *(const float4*)(prw + (b*4+r)*N_ + jA);
        float4 Bv = *(const float4*)(prw + (b*4+r)*N_ + jB);
        pj[r][0] = pk(A.x, A.y);  pj[r][1] = pk(A.z, A.w);
        pj[r][2] = pk(Bv.x, Bv.y); pj[r][3] = pk(Bv.z, Bv.w);
    }
    float4 wA = *(const float4*)(ww + b*N_ + jA);
    float4 wB = *(const float4*)(ww + b*N_ + jB);
    u64 wj[4] = { pk(wA.x,wA.y), pk(wA.z,wA.w), pk(wB.x,wB.y), pk(wB.z,wB.w) };

    u64 bw[4][4];
    #pragma unroll
    for (int r = 0; r < 4; ++r)
        #pragma unroll
        for (int k = 0; k < 4; ++k) bw[r][k] = 0ull;

    const float* Lp = L + ((size_t)(b*N_ + i0 + half))*N_ + jA;

    float4 bA0 = __ldcs((const float4*)(Lp));
    float4 bB0 = __ldcs((const float4*)(Lp + 64));
    float4 bA1 = __ldcs((const float4*)(Lp + 2*(size_t)N_));
    float4 bB1 = __ldcs((const float4*)(Lp + 2*(size_t)N_ + 64));
    float4 bA2 = __ldcs((const float4*)(Lp + 4*(size_t)N_));
    float4 bB2 = __ldcs((const float4*)(Lp + 4*(size_t)N_ + 64));

    int g = 0;

#define STEP(BA,BB) do {                                                     \
    int row = 2*g + half;                                                    \
    float4 A = BA, Bv = BB;                                                  \
    int gp = g + 3; if (gp > 63) gp = 63;                                    \
    const float* np = Lp + (size_t)(2*gp)*N_;                                \
    BA = __ldcs((const float4*)np);                                          \
    BB = __ldcs((const float4*)(np + 64));                                   \
    u64 l0 = pk(A.x,A.y), l1 = pk(A.z,A.w), l2 = pk(Bv.x,Bv.y), l3 = pk(Bv.z,Bv.w); \
    float a = s_a[row];                                                      \
    u64 av = pk(a, a);                                                       \
    u64 c0 = mul2(sub2(av, wj[0]), l0);                                      \
    u64 c1 = mul2(sub2(av, wj[1]), l1);                                      \
    u64 c2 = mul2(sub2(av, wj[2]), l2);                                      \
    u64 c3 = mul2(sub2(av, wj[3]), l3);                                      \
    float f[4];                                                              \
    _Pragma("unroll")                                                        \
    for (int r = 0; r < 4; ++r) {                                            \
        u64 t = mul2(c0, pj[r][0]);                                          \
        t = fma2(c1, pj[r][1], t);                                           \
        t = fma2(c2, pj[r][2], t);                                           \
        t = fma2(c3, pj[r][3], t);                                           \
        float x, y; upk(t, x, y); f[r] = x + y;                              \
        float pi = s_pi[r*128 + row];                                        \
        u64 pr = pk(pi, pi);                                                 \
        bw[r][0] = fma2(c0, pr, bw[r][0]);                                   \
        bw[r][1] = fma2(c1, pr, bw[r][1]);                                   \
        bw[r][2] = fma2(c2, pr, bw[r][2]);                                   \
        bw[r][3] = fma2(c3, pr, bw[r][3]);                                   \
    }                                                                        \
    u64 f01 = pk(f[0], f[1]), f23 = pk(f[2], f[3]);                          \
    _Pragma("unroll")                                                        \
    for (int m = 8; m; m >>= 1) {                                            \
        f01 = add2(f01, __shfl_xor_sync(~0u, f01, m));                       \
        f23 = add2(f23, __shfl_xor_sync(~0u, f23, m));                       \
    }                                                                        \
    if (h == 0) { SP(0, row, w) = f01; SP(1, row, w) = f23; }                \
    ++g;                                                                     \
} while (0)

    #pragma unroll 1
    for (int gb = 0; gb < 21; ++gb) {   // 63 row-pairs
        STEP(bA0, bB0);
        STEP(bA1, bB1);
        STEP(bA2, bB2);
    }
    STEP(bA0, bB0);                     // g = 63 (prefetch clamps, redundant)
#undef STEP

    // bwd: combine halves, REDG-accumulate into g_bwd
    #pragma unroll
    for (int r = 0; r < 4; ++r)
        #pragma unroll
        for (int k = 0; k < 4; ++k)
            bw[r][k] = add2(bw[r][k], __shfl_xor_sync(~0u, bw[r][k], 16));
    if (half == 0) {
        #pragma unroll
        for (int r = 0; r < 4; ++r) {
            float* dst = g_bwd + (size_t)(b*4 + r)*N_;
            float x0, x1, x2, x3, x4, x5, x6, x7;
            upk(bw[r][0], x0, x1); upk(bw[r][1], x2, x3);
            upk(bw[r][2], x4, x5); upk(bw[r][3], x6, x7);
            atomicAdd(dst + jA + 0, x0); atomicAdd(dst + jA + 1, x1);
            atomicAdd(dst + jA + 2, x2); atomicAdd(dst + jA + 3, x3);
            atomicAdd(dst + jB + 0, x4); atomicAdd(dst + jB + 1, x5);
            atomicAdd(dst + jB + 2, x6); atomicAdd(dst + jB + 3, x7);
        }
    }
    __syncthreads();

    // fwd fold + rank-1 + diag corrections; emit bwd correction g_bc
    {
        int row = tid >> 2, r = tid & 3;
        int br = b*4 + r;
        int n = i0 + row;
        const float* sp = (const float*)&SP(r >> 1, row, 0);
        float sfold = 0.f;
        #pragma unroll
        for (int w2 = 0; w2 < 16; ++w2) sfold += sp[w2*2 + (r & 1)];
        float wn  = 1.f - s_a[row];
        float pn  = p[b*N_ + n];
        float prn = s_pi[r*128 + row];
        float ell = (1.f - 2.f*wn)*s_diag[row] + wn*pn;
        g_fwd[br*N_ + n] = sfold + wn*g_P[br] - ell*prn;
        g_bc [br*N_ + n] = pn*g_S[br] - ell*prn;
    }
}

// ================= k_post: dots + exp + rw + read vector. 256 blocks x 256 =================
__global__ void __launch_bounds__(256, 1)
k_post(const float* __restrict__ mem, const float* __restrict__ controls)
{
    int b = blockIdx.x >> 5, c = blockIdx.x & 31;
    int n0 = c*64;
    int tid = threadIdx.x, warp = tid >> 5, lane = tid & 31;
    __shared__ float s_rw[4][64];
    __shared__ __align__(8) float s_key[256];
    __shared__ float s_g[12];
    __shared__ float s_b[4], s_kn[4];
    __shared__ float s_am[8][4][64];
    __shared__ float s_ac[8][4][64];

    s_key[tid] = controls[b*272 + tid];
    if (tid < 12) s_g[tid] = g_gate[b*12 + tid];
    if (tid >= 16 && tid < 20) s_b [tid-16] = g_beta[b*4 + tid-16];
    if (tid >= 20 && tid < 24) s_kn[tid-20] = g_kn [b*4 + tid-20];
    __syncthreads();

    {
        int r = tid >> 6, nl = tid & 63;
        int br = b*4 + r, n = n0 + nl;
        s_rw[r][nl] = s_g[r*3+0]*g_fwd[br*N_ + n]
                    + s_g[r*3+1]*(g_bwd[br*N_ + n] + g_bc[br*N_ + n]);
    }

    // per-lane key float2 for each r
    float2 kr[4];
    #pragma unroll
    for (int r = 0; r < 4; ++r) kr[r] = ((const float2*)s_key)[r*32 + lane];
    float beta_kn[4], betav[4];
    #pragma unroll
    for (int r = 0; r < 4; ++r) { beta_kn[r] = s_kn[r]; betav[r] = s_b[r]; }
    __syncthreads();

    float2 am[4], ac[4];
    float zs[4];
    #pragma unroll
    for (int r = 0; r < 4; ++r) { am[r].x = am[r].y = ac[r].x = ac[r].y = 0.f; zs[r] = 0.f; }

    #pragma unroll
    for (int k = 0; k < 8; ++k) {
        int nl = warp*8 + k;
        float2 m = *(const float2*)(mem + ((size_t)(b*N_ + n0 + nl))*W_ + lane*2);
        float d0 = m.x*kr[0].x + m.y*kr[0].y;
        float d1 = m.x*kr[1].x + m.y*kr[1].y;
        float d2 = m.x*kr[2].x + m.y*kr[2].y;
        float d3 = m.x*kr[3].x + m.y*kr[3].y;
        float nr = m.x*m.x + m.y*m.y;
        u64 d01 = pk(d0, d1), d23 = pk(d2, d3);
        #pragma unroll
        for (int s = 16; s; s >>= 1) {
            d01 = add2(d01, __shfl_xor_sync(~0u, d01, s));
            d23 = add2(d23, __shfl_xor_sync(~0u, d23, s));
            nr += __shfl_xor_sync(~0u, nr, s);
        }
        upk(d01, d0, d1); upk(d23, d2, d3);
        float mn = sqrtf(nr);
        float e[4];
        e[0] = __expf(betav[0]*__fdividef(d0, beta_kn[0]*mn + EPS_));
        e[1] = __expf(betav[1]*__fdividef(d1, beta_kn[1]*mn + EPS_));
        e[2] = __expf(betav[2]*__fdividef(d2, beta_kn[2]*mn + EPS_));
        e[3] = __expf(betav[3]*__fdividef(d3, beta_kn[3]*mn + EPS_));
        #pragma unroll
        for (int r = 0; r < 4; ++r) {
            float rv = s_rw[r][nl];
            am[r].x += m.x*rv;   am[r].y += m.y*rv;
            ac[r].x += m.x*e[r]; ac[r].y += m.y*e[r];
            zs[r] += e[r];
        }
    }

    // Z flush (e identical in all lanes -> lane 0 only)
    if (lane == 0) {
        #pragma unroll
        for (int r = 0; r < 4; ++r) atomicAdd(&g_Z[b*4 + r], zs[r]);
    }

    #pragma unroll
    for (int r = 0; r < 4; ++r) {
        s_am[warp][r][lane*2]   = am[r].x;
        s_am[warp][r][lane*2+1] = am[r].y;
        s_ac[warp][r][lane*2]   = ac[r].x;
        s_ac[warp][r][lane*2+1] = ac[r].y;
    }
    __syncthreads();
    {
        int r = tid >> 6, wd = tid & 63;
        float sm = 0.f, sc = 0.f;
        #pragma unroll
        for (int k = 0; k < 8; ++k) { sm += s_am[k][r][wd]; sc += s_ac[k][r][wd]; }
        atomicAdd(&g_om [(b*4 + r)*64 + wd], sm);
        atomicAdd(&g_ocw[(b*4 + r)*64 + wd], sc);
    }
}

// ================= k_fin: combine. 32 blocks x 64 =================
__global__ void __launch_bounds__(64)
k_fin(float* __restrict__ out)
{
    int br = blockIdx.x, t = threadIdx.x;
    float scale = g_gate[br*3+2] / g_Z[br];
    out[br*64 + t] = g_om[br*64 + t] + scale * g_ocw[br*64 + t];
}

// ================= launcher =================
extern "C" void kernel_launch(void* const* d_in, const int* in_sizes, int n_in,
                              void* d_out, int out_size)
{
    const float* mem      = (const float*)d_in[0];
    const float* controls = (const float*)d_in[1];
    const float* ww       = (const float*)d_in[2];
    const float* L        = (const float*)d_in[3];
    const float* p        = (const float*)d_in[4];
    const float* prw      = (const float*)d_in[5];
    float* out = (float*)d_out;

    k_pre   <<<B_*R_, 256>>>(controls, ww, p, prw);
    k_stream<<<B_*16, 512>>>(L, ww, prw, p);
    k_post  <<<B_*32, 256>>>(mem, controls);
    k_fin   <<<B_*R_, 64>>>(out);
}

// round 11
// speedup vs baseline: 1.2273x; 1.2273x over previous
#include <cuda_runtime.h>
#include <math.h>
#include <stdint.h>

#define B_ 8
#define N_ 2048
#define W_ 64
#define R_ 4
#define EPS_ 1e-8f
#define TI_ 128

typedef unsigned long long u64;

// ---------------- device scratch (zero-initialized at load) ----------------
__device__ float g_fwd [B_*R_*N_];     // raw fwd fold (corrections in k_post)
__device__ float g_bwd [B_*R_*N_];     // REDG-accumulated bwd core sums; re-zeroed by k_post
__device__ float g_cw  [B_*R_*N_];     // beta-scaled content scores
__device__ float g_ell [B_*N_];        // (1-2w)Lnn + w*p  (r-independent diag term)
__device__ float g_PSp [B_*R_*16*2];   // per-chunk P/S partials
__device__ float g_gate[B_*R_*3];
__device__ float g_P   [B_*R_];
__device__ float g_S   [B_*R_];
__device__ float g_mx  [B_*R_];
__device__ float g_inv [B_*R_];

// ---------------- f32x2 helpers ----------------
__device__ __forceinline__ u64 pk(float a, float b){
    u64 r; asm("mov.b64 %0,{%1,%2};" : "=l"(r) : "f"(a), "f"(b)); return r;
}
__device__ __forceinline__ void upk(u64 x, float& a, float& b){
    asm("mov.b64 {%0,%1},%2;" : "=f"(a), "=f"(b) : "l"(x));
}
__device__ __forceinline__ u64 add2(u64 a, u64 b){
    u64 d; asm("add.rn.f32x2 %0,%1,%2;" : "=l"(d) : "l"(a), "l"(b)); return d;
}
__device__ __forceinline__ u64 sub2(u64 a, u64 b){
    u64 d; asm("sub.rn.f32x2 %0,%1,%2;" : "=l"(d) : "l"(a), "l"(b)); return d;
}
__device__ __forceinline__ u64 mul2(u64 a, u64 b){
    u64 d; asm("mul.rn.f32x2 %0,%1,%2;" : "=l"(d) : "l"(a), "l"(b)); return d;
}
__device__ __forceinline__ u64 fma2(u64 a, u64 b, u64 c){
    u64 d; asm("fma.rn.f32x2 %0,%1,%2,%3;" : "=l"(d) : "l"(a), "l"(b), "l"(c)); return d;
}

// ================= k_fused: blocks 0-127 stream L; blocks 128-255 content dots =================
#define SP(sel,row,w) s_part[(((sel)*128 + (row))*16) + (w)]

__global__ void __launch_bounds__(512, 1)
k_fused(const float* __restrict__ L, const float* __restrict__ ww,
        const float* __restrict__ prw, const float* __restrict__ p,
        const float* __restrict__ mem, const float* __restrict__ controls)
{
    __shared__ u64   s_part[2*128*16];     // 32 KB fwd partials (stream path)
    __shared__ float s_a[TI_];
    __shared__ float s_pi[R_*TI_];
    __shared__ float s_diag[TI_];
    __shared__ __align__(16) float s_key[256];   // dots path
    __shared__ float s_kn[4];
    __shared__ float s_beta[4];
    __shared__ float s_prod[8][128];

    int tid = threadIdx.x, w = tid >> 5, lane = tid & 31;
    int half = lane >> 4, h = lane & 15;

    if (blockIdx.x >= 128) {
        // ===================== DOTS PATH (exact R8 k_dots + beta + P/S partials) ==============
        int idx = blockIdx.x - 128;
        int b = idx >> 4, chunk = idx & 15;
        int n0 = chunk * 128;

        if (tid < 256) s_key[tid] = controls[b*272 + tid];
        if (tid >= 256 && tid < 260) {
            float x = controls[b*272 + 256 + (tid - 256)];
            s_beta[tid - 256] = 1.f + ((x > 15.f) ? x : log1pf(__expf(x)));
        }
        __syncthreads();
        if (w < 4) {
            float x0 = s_key[w*64 + lane], x1 = s_key[w*64 + 32 + lane];
            float q = x0*x0 + x1*x1;
            #pragma unroll
            for (int m = 16; m; m >>= 1) q += __shfl_xor_sync(~0u, q, m);
            if (lane == 0) s_kn[w] = sqrtf(q);
        }
        // P,S chunk-partials: products into smem
        if (tid < 128) {
            int n = n0 + tid;
            float pv = p [b*N_ + n];
            float wv = ww[b*N_ + n];
            #pragma unroll
            for (int r = 0; r < 4; ++r) {
                float t = prw[(b*4+r)*N_ + n];
                s_prod[r*2+0][tid] = pv*t;
                s_prod[r*2+1][tid] = wv*t;
            }
        }
        __syncthreads();

        #pragma unroll
        for (int it = 0; it < 4; ++it) {
            int n = n0 + w*8 + it*2 + half;
            float4 m4 = *(const float4*)(mem + ((size_t)(b*N_ + n))*W_ + h*4);
            float4 k0 = *(const float4*)(s_key + 0*64 + h*4);
            float4 k1 = *(const float4*)(s_key + 1*64 + h*4);
            float4 k2 = *(const float4*)(s_key + 2*64 + h*4);
            float4 k3 = *(const float4*)(s_key + 3*64 + h*4);
            float d0 = m4.x*k0.x + m4.y*k0.y + m4.z*k0.z + m4.w*k0.w;
            float d1 = m4.x*k1.x + m4.y*k1.y + m4.z*k1.z + m4.w*k1.w;
            float d2 = m4.x*k2.x + m4.y*k2.y + m4.z*k2.z + m4.w*k2.w;
            float d3 = m4.x*k3.x + m4.y*k3.y + m4.z*k3.z + m4.w*k3.w;
            float nr = m4.x*m4.x + m4.y*m4.y + m4.z*m4.z + m4.w*m4.w;
            u64 p01 = pk(d0, d1), p23 = pk(d2, d3);
            #pragma unroll
            for (int m = 8; m; m >>= 1) {
                p01 = add2(p01, __shfl_xor_sync(~0u, p01, m));
                p23 = add2(p23, __shfl_xor_sync(~0u, p23, m));
                nr += __shfl_xor_sync(~0u, nr, m);
            }
            if (h == 0) {
                float mns = sqrtf(nr);
                float a0, a1, a2, a3;
                upk(p01, a0, a1); upk(p23, a2, a3);
                g_cw[(b*4+0)*N_ + n] = s_beta[0]*a0/(s_kn[0]*mns + EPS_);
                g_cw[(b*4+1)*N_ + n] = s_beta[1]*a1/(s_kn[1]*mns + EPS_);
                g_cw[(b*4+2)*N_ + n] = s_beta[2]*a2/(s_kn[2]*mns + EPS_);
                g_cw[(b*4+3)*N_ + n] = s_beta[3]*a3/(s_kn[3]*mns + EPS_);
            }
        }

        // reduce the 8 partial arrays: warp q reduces s_prod[q][0..127]
        if (w < 8) {
            float s = s_prod[w][lane] + s_prod[w][lane+32] + s_prod[w][lane+64] + s_prod[w][lane+96];
            #pragma unroll
            for (int m = 16; m; m >>= 1) s += __shfl_xor_sync(~0u, s, m);
            if (lane == 0) g_PSp[((b*4 + (w >> 1))*16 + chunk)*2 + (w & 1)] = s;
        }
        return;
    }

    // ===================== STREAM PATH (exact R8 k_stream; epilogue emits raw fwd + ell) =====
    int b = blockIdx.x >> 4, tile = blockIdx.x & 15, i0 = tile*TI_;

    if (tid < TI_) {
        s_a[tid]    = 1.f - ww[b*N_ + i0 + tid];
        s_diag[tid] = __ldg(L + ((size_t)(b*N_ + i0 + tid))*N_ + i0 + tid);
    }
    if (tid < R_*TI_) s_pi[tid] = prw[(b*4 + (tid >> 7))*N_ + i0 + (tid & 127)];
    __syncthreads();

    int jA = w*128 + h*4, jB = jA + 64;
    u64 pj[4][4];
    #pragma unroll
    for (int r = 0; r < 4; ++r) {
        float4 A  = *(const float4*)(prw + (b*4+r)*N_ + jA);
        float4 Bv = *(const float4*)(prw + (b*4+r)*N_ + jB);
        pj[r][0] = pk(A.x, A.y);  pj[r][1] = pk(A.z, A.w);
        pj[r][2] = pk(Bv.x, Bv.y); pj[r][3] = pk(Bv.z, Bv.w);
    }
    float4 wA = *(const float4*)(ww + b*N_ + jA);
    float4 wB = *(const float4*)(ww + b*N_ + jB);
    u64 wj[4] = { pk(wA.x,wA.y), pk(wA.z,wA.w), pk(wB.x,wB.y), pk(wB.z,wB.w) };

    u64 bw[4][4];
    #pragma unroll
    for (int r = 0; r < 4; ++r)
        #pragma unroll
        for (int k = 0; k < 4; ++k) bw[r][k] = 0ull;

    const float* Lp = L + ((size_t)(b*N_ + i0 + half))*N_ + jA;

    float4 bA0 = __ldcs((const float4*)(Lp));
    float4 bB0 = __ldcs((const float4*)(Lp + 64));
    float4 bA1 = __ldcs((const float4*)(Lp + 2*(size_t)N_));
    float4 bB1 = __ldcs((const float4*)(Lp + 2*(size_t)N_ + 64));
    float4 bA2 = __ldcs((const float4*)(Lp + 4*(size_t)N_));
    float4 bB2 = __ldcs((const float4*)(Lp + 4*(size_t)N_ + 64));

    int g = 0;

#define STEP(BA,BB) do {                                                     \
    int row = 2*g + half;                                                    \
    float4 A = BA, Bv = BB;                                                  \
    int gp = g + 3; if (gp > 63) gp = 63;                                    \
    const float* np = Lp + (size_t)(2*gp)*N_;                                \
    BA = __ldcs((const float4*)np);                                          \
    BB = __ldcs((const float4*)(np + 64));                                   \
    u64 l0 = pk(A.x,A.y), l1 = pk(A.z,A.w), l2 = pk(Bv.x,Bv.y), l3 = pk(Bv.z,Bv.w); \
    float a = s_a[row];                                                      \
    u64 av = pk(a, a);                                                       \
    u64 c0 = mul2(sub2(av, wj[0]), l0);                                      \
    u64 c1 = mul2(sub2(av, wj[1]), l1);                                      \
    u64 c2 = mul2(sub2(av, wj[2]), l2);                                      \
    u64 c3 = mul2(sub2(av, wj[3]), l3);                                      \
    float f[4];                                                              \
    _Pragma("unroll")                                                        \
    for (int r = 0; r < 4; ++r) {                                            \
        u64 t = mul2(c0, pj[r][0]);                                          \
        t = fma2(c1, pj[r][1], t);                                           \
        t = fma2(c2, pj[r][2], t);                                           \
        t = fma2(c3, pj[r][3], t);                                           \
        float x, y; upk(t, x, y); f[r] = x + y;                              \
        float pi = s_pi[r*128 + row];                                        \
        u64 pr = pk(pi, pi);                                                 \
        bw[r][0] = fma2(c0, pr, bw[r][0]);                                   \
        bw[r][1] = fma2(c1, pr, bw[r][1]);                                   \
        bw[r][2] = fma2(c2, pr, bw[r][2]);                                   \
        bw[r][3] = fma2(c3, pr, bw[r][3]);                                   \
    }                                                                        \
    u64 f01 = pk(f[0], f[1]), f23 = pk(f[2], f[3]);                          \
    _Pragma("unroll")                                                        \
    for (int m = 8; m; m >>= 1) {                                            \
        f01 = add2(f01, __shfl_xor_sync(~0u, f01, m));                       \
        f23 = add2(f23, __shfl_xor_sync(~0u, f23, m));                       \
    }                                                                        \
    if (h == 0) { SP(0, row, w) = f01; SP(1, row, w) = f23; }                \
    ++g;                                                                     \
} while (0)

    #pragma unroll 1
    for (int gb = 0; gb < 21; ++gb) {   // 63 row-pairs
        STEP(bA0, bB0);
        STEP(bA1, bB1);
        STEP(bA2, bB2);
    }
    STEP(bA0, bB0);                     // g = 63 (prefetch clamps, redundant)
#undef STEP

    // bwd: combine halves, REDG-accumulate into g_bwd (zeroed by prior k_post / static init)
    #pragma unroll
    for (int r = 0; r < 4; ++r)
        #pragma unroll
        for (int k = 0; k < 4; ++k)
            bw[r][k] = add2(bw[r][k], __shfl_xor_sync(~0u, bw[r][k], 16));
    if (half == 0) {
        #pragma unroll
        for (int r = 0; r < 4; ++r) {
            float* dst = g_bwd + (size_t)(b*4 + r)*N_;
            float x0, x1, x2, x3, x4, x5, x6, x7;
            upk(bw[r][0], x0, x1); upk(bw[r][1], x2, x3);
            upk(bw[r][2], x4, x5); upk(bw[r][3], x6, x7);
            atomicAdd(dst + jA + 0, x0); atomicAdd(dst + jA + 1, x1);
            atomicAdd(dst + jA + 2, x2); atomicAdd(dst + jA + 3, x3);
            atomicAdd(dst + jB + 0, x4); atomicAdd(dst + jB + 1, x5);
            atomicAdd(dst + jB + 2, x6); atomicAdd(dst + jB + 3, x7);
        }
    }
    __syncthreads();

    // fwd fold (raw) + emit r-independent diag term
    {
        int row = tid >> 2, r = tid & 3;
        int br = b*4 + r;
        int n = i0 + row;
        const float* sp = (const float*)&SP(r >> 1, row, 0);
        float sfold = 0.f;
        #pragma unroll
        for (int w2 = 0; w2 < 16; ++w2) sfold += sp[w2*2 + (r & 1)];
        g_fwd[br*N_ + n] = sfold;
        if (r == 0) {
            float wn = 1.f - s_a[row];
            float pn = p[b*N_ + n];
            g_ell[b*N_ + n] = (1.f - 2.f*wn)*s_diag[row] + wn*pn;
        }
    }
}

// ================= k_red: P/S partial sums, gates, softmax mx & 1/Z, zero out. 32 blocks =================
__global__ void __launch_bounds__(256)
k_red(const float* __restrict__ controls, float* __restrict__ out)
{
    int br = blockIdx.x, b = br >> 2, r = br & 3;
    int tid = threadIdx.x, warp = tid >> 5, lane = tid & 31;
    __shared__ float s_r[8];
    __shared__ float s_bc;

    if (tid < 64) out[br*64 + tid] = 0.f;

    float v[8]; float mx = -1e30f;
    #pragma unroll
    for (int k = 0; k < 8; ++k) { v[k] = g_cw[br*N_ + tid + k*256]; mx = fmaxf(mx, v[k]); }
    #pragma unroll
    for (int m = 16; m; m >>= 1) mx = fmaxf(mx, __shfl_xor_sync(~0u, mx, m));
    if (lane == 0) s_r[warp] = mx;
    __syncthreads();
    if (tid == 0) { float m2 = s_r[0]; for (int i = 1; i < 8; ++i) m2 = fmaxf(m2, s_r[i]); s_bc = m2; }
    __syncthreads();
    mx = s_bc;
    float s = 0.f;
    #pragma unroll
    for (int k = 0; k < 8; ++k) s += __expf(v[k] - mx);
    #pragma unroll
    for (int m = 16; m; m >>= 1) s += __shfl_xor_sync(~0u, s, m);
    __syncthreads();
    if (lane == 0) s_r[warp] = s;
    __syncthreads();
    if (tid == 0) {
        float t = 0.f;
        for (int i = 0; i < 8; ++i) t += s_r[i];
        g_mx[br] = mx; g_inv[br] = 1.f/t;

        float P = 0.f, S = 0.f;
        #pragma unroll
        for (int c = 0; c < 16; ++c) {
            P += g_PSp[(br*16 + c)*2 + 0];
            S += g_PSp[(br*16 + c)*2 + 1];
        }
        g_P[br] = P; g_S[br] = S;
        float e0 = controls[b*272 + 260 + r*3 + 0];
        float e1 = controls[b*272 + 260 + r*3 + 1];
        float e2 = controls[b*272 + 260 + r*3 + 2];
        float mm = fmaxf(e0, fmaxf(e1, e2));
        float x0 = __expf(e0-mm), x1 = __expf(e1-mm), x2 = __expf(e2-mm);
        float inv = 1.f/(x0+x1+x2);
        g_gate[br*3+0] = x0*inv; g_gate[br*3+1] = x1*inv; g_gate[br*3+2] = x2*inv;
    }
}

// ================= k_post: corrections + exp + rw + read vector; re-zeroes g_bwd =================
__global__ void __launch_bounds__(256, 1)
k_post(const float* __restrict__ mem, const float* __restrict__ ww,
       const float* __restrict__ p, const float* __restrict__ prw,
       float* __restrict__ out)
{
    int b = blockIdx.x >> 5, c = blockIdx.x & 31;
    int n0 = c*64;
    int tid = threadIdx.x, warp = tid >> 5, lane = tid & 31;
    __shared__ float s_rw[4][64];
    __shared__ float s_g[12];
    __shared__ float s_mx[4], s_inv[4], s_P[4], s_S[4];
    __shared__ float s_acc[8][4][64];

    if (tid < 12) s_g[tid] = g_gate[b*12 + tid];
    if (tid >= 16 && tid < 20) s_mx [tid-16] = g_mx [b*4 + tid-16];
    if (tid >= 20 && tid < 24) s_inv[tid-20] = g_inv[b*4 + tid-20];
    if (tid >= 24 && tid < 28) s_P  [tid-24] = g_P  [b*4 + tid-24];
    if (tid >= 28 && tid < 32) s_S  [tid-28] = g_S  [b*4 + tid-28];
    __syncthreads();

    {
        int r = tid >> 6, nl = tid & 63;
        int br = b*4 + r, n = n0 + nl;
        float wn  = ww[b*N_ + n];
        float pn  = p [b*N_ + n];
        float ell = g_ell[b*N_ + n];
        float prn = prw[br*N_ + n];
        float fwd = g_fwd[br*N_ + n] + wn*s_P[r] - ell*prn;
        float bwd = g_bwd[br*N_ + n] + pn*s_S[r] - ell*prn;
        float cwv = __expf(g_cw[br*N_ + n] - s_mx[r]) * s_inv[r];
        s_rw[r][nl] = s_g[r*3+0]*fwd + s_g[r*3+1]*bwd + s_g[r*3+2]*cwv;
        g_bwd[br*N_ + n] = 0.f;   // restore state for next graph replay
    }
    __syncthreads();

    float2 acc[4];
    #pragma unroll
    for (int r = 0; r < 4; ++r) { acc[r].x = 0.f; acc[r].y = 0.f; }
    #pragma unroll
    for (int k = 0; k < 8; ++k) {
        int nl = warp*8 + k;
        float2 m = *(const float2*)(mem + ((size_t)(b*N_ + n0 + nl))*W_ + lane*2);
        #pragma unroll
        for (int r = 0; r < 4; ++r) {
            float rv = s_rw[r][nl];
            acc[r].x += m.x*rv;
            acc[r].y += m.y*rv;
        }
    }
    #pragma unroll
    for (int r = 0; r < 4; ++r) {
        s_acc[warp][r][lane*2]   = acc[r].x;
        s_acc[warp][r][lane*2+1] = acc[r].y;
    }
    __syncthreads();
    {
        int r = tid >> 6, wd = tid & 63;
        float s = 0.f;
        #pragma unroll
        for (int k = 0; k < 8; ++k) s += s_acc[k][r][wd];
        atomicAdd(&out[(b*4 + r)*64 + wd], s);
    }
}

// ================= launcher =================
extern "C" void kernel_launch(void* const* d_in, const int* in_sizes, int n_in,
                              void* d_out, int out_size)
{
    const float* mem      = (const float*)d_in[0];
    const float* controls = (const float*)d_in[1];
    const float* ww       = (const float*)d_in[2];
    const float* L        = (const float*)d_in[3];
    const float* p        = (const float*)d_in[4];
    const float* prw      = (const float*)d_in[5];
    float* out = (float*)d_out;

    k_fused<<<256, 512>>>(L, ww, prw, p, mem, controls);
    k_red  <<<B_*R_, 256>>>(controls, out);
    k_post <<<B_*32, 256>>>(mem, ww, p, prw, out);
}